// round 3
// baseline (speedup 1.0000x reference)
#include <cuda_runtime.h>
#include <math.h>
#include <stdint.h>

#define TT 8192
#define DD 256
#define FF 1024
#define EE 32
#define KK 4

#define TM 64   // tokens per block tile
#define FC 64   // ffn chunk

// ---------------- scratch (static device globals; no allocation) ----------------
__device__ int   g_counts[EE];
__device__ int   g_offsets[EE + 1];
__device__ float g_probs_sum[EE];
__device__ int   g_as_e[TT * KK];
__device__ int   g_as_pos[TT * KK];
__device__ float g_as_w[TT * KK];
__device__ int   g_list_tok[TT * KK];
__device__ float g_list_w[TT * KK];

// ---------------- init ----------------
__global__ void init_kernel()
{
    int i = threadIdx.x;
    if (i < EE) { g_counts[i] = 0; g_probs_sum[i] = 0.f; }
}

// ---------------- router: 8 warps/block, 1 token/warp ----------------
__global__ __launch_bounds__(256) void router_kernel(const float* __restrict__ x,
                                                     const float* __restrict__ rw)
{
    __shared__ float rw_s[EE * 257];   // padded: bank = (e+d)&31, conflict-free
    __shared__ float xsh[8 * 260];
    __shared__ float pacc[EE];

    const int tid  = threadIdx.x;
    const int lane = tid & 31;
    const int warp = tid >> 5;

    for (int i = tid; i < EE * DD; i += 256) {
        int e = i >> 8, d = i & 255;
        rw_s[e * 257 + d] = rw[i];
    }
    if (tid < EE) pacc[tid] = 0.f;
    __syncthreads();

    const int t = blockIdx.x * 8 + warp;
    {
        const float4* xr = (const float4*)(x + (size_t)t * DD);
        float4 a = xr[lane * 2];
        float4 b = xr[lane * 2 + 1];
        *(float4*)&xsh[warp * 260 + lane * 8]     = a;
        *(float4*)&xsh[warp * 260 + lane * 8 + 4] = b;
    }
    __syncwarp();

    // lane = expert
    float acc = 0.f;
    const float* xrow  = &xsh[warp * 260];
    const float* rwrow = &rw_s[lane * 257];
#pragma unroll 8
    for (int d = 0; d < DD; d++) acc = fmaf(xrow[d], rwrow[d], acc);
    const float logit = acc;

    // full softmax -> probs accumulation (for aux loss)
    float m = logit;
#pragma unroll
    for (int o = 16; o; o >>= 1) m = fmaxf(m, __shfl_xor_sync(0xffffffffu, m, o));
    float p = expf(logit - m);
    float s = p;
#pragma unroll
    for (int o = 16; o; o >>= 1) s += __shfl_xor_sync(0xffffffffu, s, o);
    atomicAdd(&pacc[lane], p / s);

    // top-4 (lower index wins ties, matching lax.top_k)
    float lv = logit;
    float vals[KK]; int idxs[KK];
#pragma unroll
    for (int k = 0; k < KK; k++) {
        float v = lv; int id = lane;
#pragma unroll
        for (int o = 16; o; o >>= 1) {
            float v2 = __shfl_xor_sync(0xffffffffu, v, o);
            int   i2 = __shfl_xor_sync(0xffffffffu, id, o);
            if (v2 > v || (v2 == v && i2 < id)) { v = v2; id = i2; }
        }
        vals[k] = v; idxs[k] = id;
        if (lane == id) lv = __int_as_float(0xff800000);  // -inf
    }

    // softmax over top-4 (vals[0] is max)
    float ws[KK]; float sum = 0.f;
#pragma unroll
    for (int k = 0; k < KK; k++) { ws[k] = expf(vals[k] - vals[0]); sum += ws[k]; }
    const float inv = 1.f / sum;

    if (lane == 0) {
#pragma unroll
        for (int k = 0; k < KK; k++) {
            int e   = idxs[k];
            int pos = atomicAdd(&g_counts[e], 1);
            int a   = t * KK + k;
            g_as_e[a] = e; g_as_pos[a] = pos; g_as_w[a] = ws[k] * inv;
        }
    }
    __syncthreads();
    if (tid < EE) atomicAdd(&g_probs_sum[tid], pacc[tid]);
}

// ---------------- scan offsets + aux loss ----------------
__global__ void scan_aux_kernel(float* __restrict__ out, int out_size)
{
    const int tid = threadIdx.x;   // 32 threads
    int c = g_counts[tid];
    int v = c;
#pragma unroll
    for (int o = 1; o < 32; o <<= 1) {
        int n = __shfl_up_sync(0xffffffffu, v, o);
        if (tid >= o) v += n;
    }
    g_offsets[tid] = v - c;
    if (tid == 31) g_offsets[EE] = v;

    const float invT = 1.f / (float)TT;
    float part = ((float)c * invT) * (g_probs_sum[tid] * invT);
#pragma unroll
    for (int o = 16; o; o >>= 1) part += __shfl_xor_sync(0xffffffffu, part, o);
    if (tid == 0 && out_size > TT * DD) out[(size_t)TT * DD] = (float)EE * part;
}

// ---------------- build per-expert token lists ----------------
__global__ void fill_kernel()
{
    int i = blockIdx.x * blockDim.x + threadIdx.x;
    if (i < TT * KK) {
        int e    = g_as_e[i];
        int slot = g_offsets[e] + g_as_pos[i];
        g_list_tok[slot] = i >> 2;
        g_list_w[slot]   = g_as_w[i];
    }
}

// ---------------- fused expert FFN (SwiGLU) ----------------
// shared layout (floats):
constexpr int XS_F = 256 * 68;     // XsT[d][r], padded stride 68
constexpr int HS_F = 64 * 68;      // HsT[f][r]
constexpr int WD_F = 256 * 65;     // Wd[dcol][fl], stride 65 (union with WGT/WUT staging)
constexpr int SMEM_FLOATS = XS_F + HS_F + WD_F + 64 + 64;
constexpr int SMEM_BYTES  = SMEM_FLOATS * 4;   // 154112 B

__global__ __launch_bounds__(256, 1)
void moe_expert_kernel(const float* __restrict__ x,
                       const float* __restrict__ w_gate,
                       const float* __restrict__ w_up,
                       const float* __restrict__ w_down,
                       float* __restrict__ out)
{
    extern __shared__ float sm[];
    float* XsT = sm;                  // [256][68]
    float* HsT = XsT + XS_F;          // [64][68]
    float* WD  = HsT + HS_F;          // [256][65]   (union)
    float* WGT = WD;                  // [32][68]
    float* WUT = WD + 32 * 68;        // [32][68]
    int*   toks = (int*)(WD + WD_F);
    float* wsh  = (float*)(toks + TM);

    const int e     = blockIdx.y;
    const int base  = g_offsets[e];
    const int count = g_offsets[e + 1] - base;
    const int m0    = blockIdx.x * TM;
    if (m0 >= count) return;

    const int tid  = threadIdx.x;
    const int tx   = tid & 15;
    const int ty   = tid >> 4;
    const int lane = tid & 31;
    const int warp = tid >> 5;

    if (tid < TM) {
        int r = m0 + tid;
        if (r < count) { toks[tid] = g_list_tok[base + r]; wsh[tid] = g_list_w[base + r]; }
        else           { toks[tid] = -1;                   wsh[tid] = 0.f; }
    }
    __syncthreads();

    // load X tile transposed into shared
    for (int r = warp; r < TM; r += 8) {
        int t = toks[r];
        float4 a = make_float4(0.f, 0.f, 0.f, 0.f), b = a;
        if (t >= 0) {
            const float4* xr = (const float4*)(x + (size_t)t * DD);
            a = xr[lane * 2]; b = xr[lane * 2 + 1];
        }
        int d = lane * 8;
        XsT[(d + 0) * 68 + r] = a.x; XsT[(d + 1) * 68 + r] = a.y;
        XsT[(d + 2) * 68 + r] = a.z; XsT[(d + 3) * 68 + r] = a.w;
        XsT[(d + 4) * 68 + r] = b.x; XsT[(d + 5) * 68 + r] = b.y;
        XsT[(d + 6) * 68 + r] = b.z; XsT[(d + 7) * 68 + r] = b.w;
    }

    const float* wg_e = w_gate + (size_t)e * FF * DD;
    const float* wu_e = w_up   + (size_t)e * FF * DD;
    const float* wd_e = w_down + (size_t)e * DD * FF;

    float acc[4][16];
#pragma unroll
    for (int i = 0; i < 4; i++)
#pragma unroll
        for (int j = 0; j < 16; j++) acc[i][j] = 0.f;

    for (int f0 = 0; f0 < FF; f0 += FC) {
        float G[4][4], U[4][4];
#pragma unroll
        for (int i = 0; i < 4; i++)
#pragma unroll
            for (int j = 0; j < 4; j++) { G[i][j] = 0.f; U[i][j] = 0.f; }

        // ---- GEMM1: G = X Wg^T, U = X Wu^T over K=D=256 in 32-slices ----
        for (int k0 = 0; k0 < DD; k0 += 32) {
            __syncthreads();   // protects WD/WGT/WUT union + XsT visibility
#pragma unroll
            for (int i = 0; i < 2; i++) {
                int idx4 = tid + i * 256;        // 512 float4 per matrix
                int fl = idx4 >> 3;
                int d4 = idx4 & 7;
                const float4 g4 = *(const float4*)(wg_e + (size_t)(f0 + fl) * DD + k0 + d4 * 4);
                const float4 u4 = *(const float4*)(wu_e + (size_t)(f0 + fl) * DD + k0 + d4 * 4);
                int dl = d4 * 4;
                WGT[(dl + 0) * 68 + fl] = g4.x; WGT[(dl + 1) * 68 + fl] = g4.y;
                WGT[(dl + 2) * 68 + fl] = g4.z; WGT[(dl + 3) * 68 + fl] = g4.w;
                WUT[(dl + 0) * 68 + fl] = u4.x; WUT[(dl + 1) * 68 + fl] = u4.y;
                WUT[(dl + 2) * 68 + fl] = u4.z; WUT[(dl + 3) * 68 + fl] = u4.w;
            }
            __syncthreads();
#pragma unroll 8
            for (int kk = 0; kk < 32; kk++) {
                const float4 xr4 = *(const float4*)&XsT[(k0 + kk) * 68 + 4 * ty];
                const float4 g4  = *(const float4*)&WGT[kk * 68 + 4 * tx];
                const float4 u4  = *(const float4*)&WUT[kk * 68 + 4 * tx];
                const float xa[4] = {xr4.x, xr4.y, xr4.z, xr4.w};
                const float ga[4] = {g4.x, g4.y, g4.z, g4.w};
                const float ua[4] = {u4.x, u4.y, u4.z, u4.w};
#pragma unroll
                for (int i = 0; i < 4; i++)
#pragma unroll
                    for (int j = 0; j < 4; j++) {
                        G[i][j] = fmaf(xa[i], ga[j], G[i][j]);
                        U[i][j] = fmaf(xa[i], ua[j], U[i][j]);
                    }
            }
        }

        // ---- h = silu(G) * U -> HsT[f][r] ----
#pragma unroll
        for (int c = 0; c < 4; c++)
#pragma unroll
            for (int i = 0; i < 4; i++) {
                float g = G[i][c];
                float h = (g / (1.f + expf(-g))) * U[i][c];
                HsT[(4 * tx + c) * 68 + 4 * ty + i] = h;
            }
        __syncthreads();   // all GEMM1 reads + HsT writes complete

        // ---- stage Wd chunk: WD[dcol][fl] (stride 65, conflict-free r/w) ----
#pragma unroll 4
        for (int i = 0; i < 64; i++) {
            int idx  = tid + i * 256;
            int dcol = idx >> 6;
            int fl   = idx & 63;
            WD[dcol * 65 + fl] = wd_e[(size_t)dcol * FF + f0 + fl];
        }
        __syncthreads();

        // ---- GEMM2: acc += h Wd^T ----
#pragma unroll 4
        for (int kk = 0; kk < FC; kk++) {
            const float4 h4 = *(const float4*)&HsT[kk * 68 + 4 * ty];
            const float hv[4] = {h4.x, h4.y, h4.z, h4.w};
            float wv[16];
#pragma unroll
            for (int j = 0; j < 16; j++) wv[j] = WD[(tx + 16 * j) * 65 + kk];
#pragma unroll
            for (int i = 0; i < 4; i++)
#pragma unroll
                for (int j = 0; j < 16; j++)
                    acc[i][j] = fmaf(hv[i], wv[j], acc[i][j]);
        }
    }

    // ---- weighted scatter-add ----
#pragma unroll
    for (int i = 0; i < 4; i++) {
        int r = 4 * ty + i;
        int t = toks[r];
        if (t < 0) continue;
        float w = wsh[r];
        float* orow = out + (size_t)t * DD;
#pragma unroll
        for (int j = 0; j < 16; j++)
            atomicAdd(&orow[tx + 16 * j], w * acc[i][j]);
    }
}

// ---------------- launch ----------------
extern "C" void kernel_launch(void* const* d_in, const int* in_sizes, int n_in,
                              void* d_out, int out_size)
{
    const float* x  = (const float*)d_in[0];
    const float* rw = (const float*)d_in[1];
    const float* wg = (const float*)d_in[2];
    const float* wu = (const float*)d_in[3];
    const float* wd = (const float*)d_in[4];
    float* out = (float*)d_out;

    cudaMemsetAsync(d_out, 0, (size_t)out_size * sizeof(float));
    init_kernel<<<1, 32>>>();
    router_kernel<<<TT / 8, 256>>>(x, rw);
    scan_aux_kernel<<<1, 32>>>(out, out_size);
    fill_kernel<<<(TT * KK + 255) / 256, 256>>>();

    cudaFuncSetAttribute(moe_expert_kernel,
                         cudaFuncAttributeMaxDynamicSharedMemorySize, SMEM_BYTES);
    dim3 grid(TT / TM, EE);   // 128 tiles x 32 experts; tiles beyond count exit early
    moe_expert_kernel<<<grid, 256, SMEM_BYTES>>>(x, wg, wu, wd, out);
}